// round 1
// baseline (speedup 1.0000x reference)
#include <cuda_runtime.h>
#include <math.h>

#define NN 100000
#define EE 6400000

// ---------------- scratch (device globals; no allocations allowed) ----------
__device__ int    g_src[EE];
__device__ int    g_dst[EE];
__device__ float  g_deg [NN];
__device__ float  g_qsum[NN];
__device__ float  g_net [NN];
__device__ float  g_w0  [NN];
__device__ float  g_c1  [NN];
__device__ float  g_c2  [NN];
__device__ float  g_Ax  [NN];
__device__ double g_red [16];
__device__ int    g_is64[4];   // [0]=edge_index, [1]=col_ind, [2]=row_idx

// ---------------- helpers ----------------------------------------------------
__device__ __forceinline__ double warpSumD(double v) {
#pragma unroll
    for (int o = 16; o; o >>= 1) v += __shfl_down_sync(0xffffffffu, v, o);
    return v;
}

// ---------------- kernels -----------------------------------------------------

// Detect whether index arrays are int64 or int32: values are < 2^17, so for an
// int64 layout every odd 32-bit word is the (zero) high half. Any nonzero odd
// word => int32. Deterministic for this data.
__global__ void k_detect(const void* eidx, long long n_eidx,
                         const void* cind, long long n_e,
                         const void* ridx) {
    __shared__ int nz[3];
    if (threadIdx.x < 3) nz[threadIdx.x] = 0;
    __syncthreads();
    const int* arr[3] = { (const int*)eidx, (const int*)cind, (const int*)ridx };
    long long  cnt[3] = { n_eidx, n_e, n_e };
    for (int a = 0; a < 3; a++) {
        const int* p = arr[a];
        long long  M = cnt[a];
        long long  step = M / 512; if (step < 2) step = 2;
        for (int k = threadIdx.x; k < 512; k += blockDim.x) {
            long long j = ((long long)k * step) | 1LL;
            if (j < M && p[j] != 0) atomicOr(&nz[a], 1);
        }
    }
    __syncthreads();
    if (threadIdx.x < 3) g_is64[threadIdx.x] = nz[threadIdx.x] ? 0 : 1;
}

__global__ void k_zero(int n) {
    int i = blockIdx.x * blockDim.x + threadIdx.x;
    if (i < n) {
        g_deg[i] = 0.f; g_qsum[i] = 0.f; g_net[i] = 0.f;
        g_c1[i] = 0.f;  g_c2[i] = 0.f;  g_Ax[i] = 0.f;
    }
    if (blockIdx.x == 0 && threadIdx.x < 16) g_red[threadIdx.x] = 0.0;
}

// Pass A: per-edge quality / degree / flux scatter; cache src/dst as int32.
__global__ void k_edgeA(const void* __restrict__ eidx,
                        const float* __restrict__ pred,
                        const float* __restrict__ feats,
                        long long e) {
    long long i = (long long)blockIdx.x * blockDim.x + threadIdx.x;
    if (i >= e) return;
    int s, d;
    if (g_is64[0]) {
        const long long* p = (const long long*)eidx;
        s = (int)p[i]; d = (int)p[e + i];
    } else {
        const int* p = (const int*)eidx;
        s = p[i]; d = p[e + i];
    }
    g_src[i] = s; g_dst[i] = d;
    float ps = pred[s], pd = pred[d];
    float dx = feats[(size_t)s * 8]     - feats[(size_t)d * 8];
    float dy = feats[(size_t)s * 8 + 1] - feats[(size_t)d * 8 + 1];
    float el = sqrtf(dx * dx + dy * dy + 1e-12f);
    float flux = ps - pd;
    float q = el * fabsf(flux);
    atomicAdd(&g_qsum[d], q);
    atomicAdd(&g_deg[d], 1.0f);
    atomicAdd(&g_net[d], flux);
}

// w0_raw = 1 + qsum/deg; reduce sum(w0_raw) for the mean.
__global__ void k_node1(int n) {
    int i = blockIdx.x * blockDim.x + threadIdx.x;
    double local = 0.0;
    if (i < n) {
        float deg = fmaxf(g_deg[i], 1.0f);
        float w = 1.0f + g_qsum[i] / deg;
        g_w0[i] = w;
        local = (double)w;
    }
    double s = warpSumD(local);
    if ((threadIdx.x & 31) == 0) atomicAdd(&g_red[0], s);
}

// normalize: w0 = w0_raw / mean(w0_raw)
__global__ void k_node2(int n) {
    int i = blockIdx.x * blockDim.x + threadIdx.x;
    if (i >= n) return;
    double mean = g_red[0] / (double)n;
    g_w0[i] = (float)((double)g_w0[i] / mean);
}

__global__ void k_hop1(long long e) {
    long long i = (long long)blockIdx.x * blockDim.x + threadIdx.x;
    if (i >= e) return;
    atomicAdd(&g_c1[g_dst[i]], g_w0[g_src[i]]);
}

__global__ void k_hop1n(int n) {
    int i = blockIdx.x * blockDim.x + threadIdx.x;
    if (i >= n) return;
    g_c1[i] /= fmaxf(g_deg[i], 1.0f);
}

__global__ void k_hop2(long long e) {
    long long i = (long long)blockIdx.x * blockDim.x + threadIdx.x;
    if (i >= e) return;
    atomicAdd(&g_c2[g_dst[i]], g_c1[g_src[i]]);
}

// Ax = segment_sum(vals * pred[col_ind], row_idx). row_idx is SORTED:
// warp-segmented inclusive scan, only segment tails issue atomics.
__global__ void k_ax(const void* __restrict__ cind,
                     const void* __restrict__ ridx,
                     const float* __restrict__ vals,
                     const float* __restrict__ pred,
                     long long e) {
    long long i = (long long)blockIdx.x * blockDim.x + threadIdx.x;
    int lane = threadIdx.x & 31;
    int r = -1; float v = 0.f;
    if (i < e) {
        int c = g_is64[1] ? (int)((const long long*)cind)[i] : ((const int*)cind)[i];
        r     = g_is64[2] ? (int)((const long long*)ridx)[i] : ((const int*)ridx)[i];
        v = vals[i] * pred[c];
    }
#pragma unroll
    for (int off = 1; off < 32; off <<= 1) {
        float ov = __shfl_up_sync(0xffffffffu, v, off);
        int   orr = __shfl_up_sync(0xffffffffu, r, off);
        if (lane >= off && orr == r) v += ov;
    }
    int rn = __shfl_down_sync(0xffffffffu, r, 1);
    if (r >= 0 && (lane == 31 || rn != r)) atomicAdd(&g_Ax[r], v);
}

// Final node pass: all loss terms reduced in double.
// g_red mapping: 1=pde_sum, 2/3=inlet s/c, 4/5=outlet s/c, 6/7=wall s/c,
//                8/9=ic s/c, 10=cons_sum
__global__ void k_final(const float* __restrict__ pred,
                        const float* __restrict__ b,
                        const float* __restrict__ icv,
                        const unsigned char* __restrict__ icm,
                        const unsigned char* __restrict__ inm,
                        const unsigned char* __restrict__ outm,
                        const unsigned char* __restrict__ wm,
                        int n) {
    int i = blockIdx.x * blockDim.x + threadIdx.x;
    double acc[10];
#pragma unroll
    for (int q = 0; q < 10; q++) acc[q] = 0.0;
    if (i < n) {
        float deg = fmaxf(g_deg[i], 1.0f);
        float wc = g_w0[i] + 0.5f * g_c1[i] + 0.25f * (g_c2[i] / deg);
        float res = g_Ax[i] - b[i];
        acc[0] = (double)(wc * res * res);
        float p = pred[i];
        if (inm[i])  { float d2 = p - 0.1f;    acc[1] = (double)(d2 * d2); acc[2] = 1.0; }
        if (outm[i]) {                          acc[3] = (double)(p * p);  acc[4] = 1.0; }
        if (wm[i])   {                          acc[5] = (double)(p * p);  acc[6] = 1.0; }
        if (icm[i])  { float d2 = p - icv[i];   acc[7] = (double)(d2 * d2); acc[8] = 1.0; }
        float net = g_net[i];
        acc[9] = (double)net * (double)net;
    }
#pragma unroll
    for (int q = 0; q < 10; q++) {
        double s = warpSumD(acc[q]);
        if ((threadIdx.x & 31) == 0) atomicAdd(&g_red[1 + q], s);
    }
}

__global__ void k_combine(float* out, int n) {
    double N = (double)n;
    double pde  = g_red[1] / N;
    double bc   = g_red[2] / fmax(g_red[3], 1.0)
                + g_red[4] / fmax(g_red[5], 1.0)
                + g_red[6] / fmax(g_red[7], 1.0);
    double ic   = g_red[8] / fmax(g_red[9], 1.0);
    double cons = g_red[10] / N;
    out[0] = (float)(pde + bc + ic + cons);
}

// ---------------- launch ------------------------------------------------------
extern "C" void kernel_launch(void* const* d_in, const int* in_sizes, int n_in,
                              void* d_out, int out_size) {
    const float* pred  = (const float*)d_in[0];
    const float* feats = (const float*)d_in[1];
    const float* b     = (const float*)d_in[2];
    const float* vals  = (const float*)d_in[3];
    const float* icv   = (const float*)d_in[4];
    // d_in[5] = row_ptr (unused by the reference)
    const void* cind   = d_in[6];
    const void* ridx   = d_in[7];
    const void* eidx   = d_in[8];
    const unsigned char* icm  = (const unsigned char*)d_in[9];
    const unsigned char* inm  = (const unsigned char*)d_in[10];
    const unsigned char* outm = (const unsigned char*)d_in[11];
    const unsigned char* wm   = (const unsigned char*)d_in[12];

    int       n = in_sizes[0];
    long long e = (long long)in_sizes[3];

    int nb_n = (n + 255) / 256;
    unsigned nb_e = (unsigned)((e + 255) / 256);

    k_detect<<<1, 256>>>(eidx, 2 * e, cind, e, ridx);
    k_zero  <<<nb_n, 256>>>(n);
    k_edgeA <<<nb_e, 256>>>(eidx, pred, feats, e);
    k_node1 <<<nb_n, 256>>>(n);
    k_node2 <<<nb_n, 256>>>(n);
    k_hop1  <<<nb_e, 256>>>(e);
    k_hop1n <<<nb_n, 256>>>(n);
    k_hop2  <<<nb_e, 256>>>(e);
    k_ax    <<<nb_e, 256>>>(cind, ridx, vals, pred, e);
    k_final <<<nb_n, 256>>>(pred, b, icv, icm, inm, outm, wm, n);
    k_combine<<<1, 1>>>((float*)d_out, n);
}

// round 2
// speedup vs baseline: 1.1910x; 1.1910x over previous
#include <cuda_runtime.h>
#include <math.h>

#define NNODES 100000
#define NEDGES 6400000

// ---------------- scratch (device globals; no allocations allowed) ----------
// g_acc: x = qsum, y = net(flux sum), z = deg, w = c1_raw (filled by hop1)
__device__ float4 g_acc[NNODES];
__device__ float  g_w0 [NNODES];   // w0 raw (un-normalized)
__device__ float  g_inv[NNODES];   // 1 / max(deg,1)
__device__ float  g_c2 [NNODES];
__device__ float  g_Ax [NNODES];
__device__ int2   g_sd [NEDGES];   // cached (src,dst) as int32
__device__ double g_red[16];
__device__ int    g_is64[4];       // [0]=edge_index, [1]=col_ind, [2]=row_idx

// ---------------- helpers ----------------------------------------------------
__device__ __forceinline__ double warpSumD(double v) {
#pragma unroll
    for (int o = 16; o; o >>= 1) v += __shfl_down_sync(0xffffffffu, v, o);
    return v;
}

__device__ __forceinline__ void redAddV4(float4* p, float x, float y, float z, float w) {
    asm volatile("red.global.add.v4.f32 [%0], {%1, %2, %3, %4};"
                 :: "l"(p), "f"(x), "f"(y), "f"(z), "f"(w) : "memory");
}

// ---------------- kernels -----------------------------------------------------

// Zero scratch; block 0 additionally detects int64-vs-int32 index layout
// (values < 2^17, so for int64 every odd 32-bit word is zero).
__global__ void k_init(const void* eidx, long long n_eidx,
                       const void* cind, long long n_e,
                       const void* ridx, int n) {
    int i = blockIdx.x * blockDim.x + threadIdx.x;
    if (i < n) {
        g_acc[i] = make_float4(0.f, 0.f, 0.f, 0.f);
        g_c2[i]  = 0.f;
        g_Ax[i]  = 0.f;
    }
    if (blockIdx.x == 0) {
        if (threadIdx.x < 16) g_red[threadIdx.x] = 0.0;
        __shared__ int nz[3];
        if (threadIdx.x < 3) nz[threadIdx.x] = 0;
        __syncthreads();
        const int* arr[3] = { (const int*)eidx, (const int*)cind, (const int*)ridx };
        long long  cnt[3] = { n_eidx, n_e, n_e };
        for (int a = 0; a < 3; a++) {
            const int* p = arr[a];
            long long  M = cnt[a];
            long long  step = M / 512; if (step < 2) step = 2;
            for (int k = threadIdx.x; k < 512; k += blockDim.x) {
                long long j = ((long long)k * step) | 1LL;
                if (j < M && p[j] != 0) atomicOr(&nz[a], 1);
            }
        }
        __syncthreads();
        if (threadIdx.x < 3) g_is64[threadIdx.x] = nz[threadIdx.x] ? 0 : 1;
    }
}

// Fused: blocks [0, nbE) do the edge scatter pass; blocks [nbE, 2*nbE) do the
// independent SpMV (Ax) pass. Overlaps the Ax HBM stream with the
// atomic-bound edge pass.
__global__ void k_edge_ax(const void* __restrict__ eidx,
                          const float* __restrict__ pred,
                          const float* __restrict__ feats,
                          const void*  __restrict__ cind,
                          const void*  __restrict__ ridx,
                          const float* __restrict__ vals,
                          long long e, unsigned nbE) {
    if (blockIdx.x < nbE) {
        // ---- edge pass: quality / flux / degree, one v4 reduction per edge
        long long i = (long long)blockIdx.x * blockDim.x + threadIdx.x;
        if (i >= e) return;
        int s, d;
        if (g_is64[0]) {
            const long long* p = (const long long*)eidx;
            s = (int)p[i]; d = (int)p[e + i];
        } else {
            const int* p = (const int*)eidx;
            s = p[i]; d = p[e + i];
        }
        g_sd[i] = make_int2(s, d);
        float ps = __ldg(&pred[s]), pd = __ldg(&pred[d]);
        float dx = __ldg(&feats[(size_t)s * 8])     - __ldg(&feats[(size_t)d * 8]);
        float dy = __ldg(&feats[(size_t)s * 8 + 1]) - __ldg(&feats[(size_t)d * 8 + 1]);
        float el = sqrtf(dx * dx + dy * dy + 1e-12f);
        float flux = ps - pd;
        float q = el * fabsf(flux);
        redAddV4(&g_acc[d], q, flux, 1.0f, 0.0f);
    } else {
        // ---- Ax = segment_sum(vals * pred[col_ind], row_idx); row_idx sorted
        long long i = (long long)(blockIdx.x - nbE) * blockDim.x + threadIdx.x;
        int lane = threadIdx.x & 31;
        int r = -1; float v = 0.f;
        if (i < e) {
            int c = g_is64[1] ? (int)((const long long*)cind)[i] : ((const int*)cind)[i];
            r     = g_is64[2] ? (int)((const long long*)ridx)[i] : ((const int*)ridx)[i];
            v = vals[i] * __ldg(&pred[c]);
        }
#pragma unroll
        for (int off = 1; off < 32; off <<= 1) {
            float ov = __shfl_up_sync(0xffffffffu, v, off);
            int   orr = __shfl_up_sync(0xffffffffu, r, off);
            if (lane >= off && orr == r) v += ov;
        }
        int rn = __shfl_down_sync(0xffffffffu, r, 1);
        if (r >= 0 && (lane == 31 || rn != r)) atomicAdd(&g_Ax[r], v);
    }
}

// w0_raw = 1 + qsum/deg, invdeg; block-reduced sum(w0_raw) for the deferred mean.
__global__ void k_node1(int n) {
    __shared__ double sm[8];
    int i = blockIdx.x * blockDim.x + threadIdx.x;
    double local = 0.0;
    if (i < n) {
        float4 a = g_acc[i];
        float deg = fmaxf(a.z, 1.0f);
        float inv = 1.0f / deg;
        float w = 1.0f + a.x * inv;
        g_w0[i]  = w;
        g_inv[i] = inv;
        local = (double)w;
    }
    int lane = threadIdx.x & 31, wp = threadIdx.x >> 5;
    double s = warpSumD(local);
    if (lane == 0) sm[wp] = s;
    __syncthreads();
    if (wp == 0) {
        s = (lane < 8) ? sm[lane] : 0.0;
        s = warpSumD(s);
        if (lane == 0) atomicAdd(&g_red[0], s);
    }
}

// hop1: c1_raw[d] += w0_raw[src]   (division by deg deferred)
__global__ void k_hop1(long long e) {
    long long i = (long long)blockIdx.x * blockDim.x + threadIdx.x;
    if (i >= e) return;
    int2 sd = g_sd[i];
    atomicAdd(((float*)&g_acc[sd.y]) + 3, __ldg(&g_w0[sd.x]));
}

// hop2: c2_raw[d] += c1[src] = c1_raw[src] * invdeg[src]
__global__ void k_hop2(long long e) {
    long long i = (long long)blockIdx.x * blockDim.x + threadIdx.x;
    if (i >= e) return;
    int2 sd = g_sd[i];
    float c1 = __ldg(((const float*)&g_acc[sd.x]) + 3) * __ldg(&g_inv[sd.x]);
    atomicAdd(&g_c2[sd.y], c1);
}

// Final node pass: all loss terms, block-reduced in double, then 10 atomics/block.
// g_red: 1=pde_raw_sum, 2/3=inlet s/c, 4/5=outlet s/c, 6/7=wall s/c,
//        8/9=ic s/c, 10=cons_sum
__global__ void k_final(const float* __restrict__ pred,
                        const float* __restrict__ b,
                        const float* __restrict__ icv,
                        const unsigned char* __restrict__ icm,
                        const unsigned char* __restrict__ inm,
                        const unsigned char* __restrict__ outm,
                        const unsigned char* __restrict__ wm,
                        int n) {
    __shared__ double sm[10][8];
    int i = blockIdx.x * blockDim.x + threadIdx.x;
    double acc[10];
#pragma unroll
    for (int q = 0; q < 10; q++) acc[q] = 0.0;
    if (i < n) {
        float4 a = g_acc[i];
        float inv = g_inv[i];
        float c1 = a.w * inv;
        float wc = g_w0[i] + 0.5f * c1 + 0.25f * (g_c2[i] * inv);
        float res = g_Ax[i] - b[i];
        acc[0] = (double)(wc * res * res);          // pde, un-normalized
        float p = pred[i];
        if (inm[i])  { float t = p - 0.1f;  acc[1] = (double)(t * t); acc[2] = 1.0; }
        if (outm[i]) {                      acc[3] = (double)(p * p); acc[4] = 1.0; }
        if (wm[i])   {                      acc[5] = (double)(p * p); acc[6] = 1.0; }
        if (icm[i])  { float t = p - icv[i]; acc[7] = (double)(t * t); acc[8] = 1.0; }
        acc[9] = (double)a.y * (double)a.y;         // net^2
    }
    int lane = threadIdx.x & 31, wp = threadIdx.x >> 5;
#pragma unroll
    for (int q = 0; q < 10; q++) {
        double s = warpSumD(acc[q]);
        if (lane == 0) sm[q][wp] = s;
    }
    __syncthreads();
    if (wp == 0) {
#pragma unroll
        for (int q = 0; q < 10; q++) {
            double s = (lane < 8) ? sm[q][lane] : 0.0;
            s = warpSumD(s);
            if (lane == 0) atomicAdd(&g_red[1 + q], s);
        }
    }
}

__global__ void k_combine(float* out) {
    // pde = (sum wc_raw*r^2 / N) / mean(w0_raw) = red[1] / red[0]
    double pde  = g_red[1] / g_red[0];
    double bc   = g_red[2] / fmax(g_red[3], 1.0)
                + g_red[4] / fmax(g_red[5], 1.0)
                + g_red[6] / fmax(g_red[7], 1.0);
    double ic   = g_red[8] / fmax(g_red[9], 1.0);
    double N    = (double)NNODES;
    double cons = g_red[10] / N;
    out[0] = (float)(pde + bc + ic + cons);
}

// ---------------- launch ------------------------------------------------------
extern "C" void kernel_launch(void* const* d_in, const int* in_sizes, int n_in,
                              void* d_out, int out_size) {
    const float* pred  = (const float*)d_in[0];
    const float* feats = (const float*)d_in[1];
    const float* b     = (const float*)d_in[2];
    const float* vals  = (const float*)d_in[3];
    const float* icv   = (const float*)d_in[4];
    // d_in[5] = row_ptr (unused by the reference)
    const void* cind   = d_in[6];
    const void* ridx   = d_in[7];
    const void* eidx   = d_in[8];
    const unsigned char* icm  = (const unsigned char*)d_in[9];
    const unsigned char* inm  = (const unsigned char*)d_in[10];
    const unsigned char* outm = (const unsigned char*)d_in[11];
    const unsigned char* wm   = (const unsigned char*)d_in[12];

    int       n = in_sizes[0];
    long long e = (long long)in_sizes[3];

    int      nb_n = (n + 255) / 256;
    unsigned nb_e = (unsigned)((e + 255) / 256);

    k_init   <<<nb_n, 256>>>(eidx, 2 * e, cind, e, ridx, n);
    k_edge_ax<<<2 * nb_e, 256>>>(eidx, pred, feats, cind, ridx, vals, e, nb_e);
    k_node1  <<<nb_n, 256>>>(n);
    k_hop1   <<<nb_e, 256>>>(e);
    k_hop2   <<<nb_e, 256>>>(e);
    k_final  <<<nb_n, 256>>>(pred, b, icv, icm, inm, outm, wm, n);
    k_combine<<<1, 1>>>((float*)d_out);
}

// round 3
// speedup vs baseline: 1.5435x; 1.2959x over previous
#include <cuda_runtime.h>
#include <math.h>

#define NNODES 100000
#define NEDGES 6400000

// ---------------- scratch (device globals; no allocations allowed) ----------
// g_acc: x = qsum, y = net(flux sum), z = deg, w = c1_raw (filled by hop1)
__device__ float4 g_acc[NNODES];
__device__ float4 g_pk [NNODES];   // (pred, coordx, coordy, 0) packed for 1-sector gather
__device__ float  g_w0 [NNODES];   // w0 raw (un-normalized)
__device__ float  g_inv[NNODES];   // 1 / max(deg,1)
__device__ float  g_c1n[NNODES];   // c1_raw * invdeg
__device__ float  g_c2 [NNODES];
__device__ float  g_Ax [NNODES];
__device__ int2   g_sd [NEDGES];   // cached (src,dst) as int32
__device__ double g_red[16];
__device__ int    g_is64[4];       // [0]=edge_index, [1]=col_ind, [2]=row_idx

// ---------------- helpers ----------------------------------------------------
__device__ __forceinline__ double warpSumD(double v) {
#pragma unroll
    for (int o = 16; o; o >>= 1) v += __shfl_down_sync(0xffffffffu, v, o);
    return v;
}

__device__ __forceinline__ void redAddV4(float4* p, float x, float y, float z, float w) {
    asm volatile("red.global.add.v4.f32 [%0], {%1, %2, %3, %4};"
                 :: "l"(p), "f"(x), "f"(y), "f"(z), "f"(w) : "memory");
}

// ---------------- kernels -----------------------------------------------------

// Zero scratch + build packed node record; block 0 also detects int64 vs int32
// index layout (values < 2^17, so for int64 every odd 32-bit word is zero).
__global__ void k_init(const void* eidx, long long n_eidx,
                       const void* cind, long long n_e,
                       const void* ridx,
                       const float* __restrict__ pred,
                       const float* __restrict__ feats, int n) {
    int i = blockIdx.x * blockDim.x + threadIdx.x;
    if (i < n) {
        g_acc[i] = make_float4(0.f, 0.f, 0.f, 0.f);
        g_c2[i]  = 0.f;
        g_Ax[i]  = 0.f;
        g_pk[i]  = make_float4(pred[i], feats[(size_t)i * 8], feats[(size_t)i * 8 + 1], 0.f);
    }
    if (blockIdx.x == 0) {
        if (threadIdx.x < 16) g_red[threadIdx.x] = 0.0;
        __shared__ int nz[3];
        if (threadIdx.x < 3) nz[threadIdx.x] = 0;
        __syncthreads();
        const int* arr[3] = { (const int*)eidx, (const int*)cind, (const int*)ridx };
        long long  cnt[3] = { n_eidx, n_e, n_e };
        for (int a = 0; a < 3; a++) {
            const int* p = arr[a];
            long long  M = cnt[a];
            long long  step = M / 512; if (step < 2) step = 2;
            for (int k = threadIdx.x; k < 512; k += blockDim.x) {
                long long j = ((long long)k * step) | 1LL;
                if (j < M && p[j] != 0) atomicOr(&nz[a], 1);
            }
        }
        __syncthreads();
        if (threadIdx.x < 3) g_is64[threadIdx.x] = nz[threadIdx.x] ? 0 : 1;
    }
}

// Fused: blocks [0, nbE) edge scatter pass; blocks [nbE, 2*nbE) independent SpMV.
__global__ void k_edge_ax(const void* __restrict__ eidx,
                          const float* __restrict__ pred,
                          const void*  __restrict__ cind,
                          const void*  __restrict__ ridx,
                          const float* __restrict__ vals,
                          long long e, unsigned nbE) {
    if (blockIdx.x < nbE) {
        // ---- edge pass: 2 packed gathers + 1 v4 reduction per edge
        long long i = (long long)blockIdx.x * blockDim.x + threadIdx.x;
        if (i >= e) return;
        int s, d;
        if (g_is64[0]) {
            const long long* p = (const long long*)eidx;
            s = (int)p[i]; d = (int)p[e + i];
        } else {
            const int* p = (const int*)eidx;
            s = p[i]; d = p[e + i];
        }
        g_sd[i] = make_int2(s, d);
        float4 ns = __ldg(&g_pk[s]);
        float4 nd = __ldg(&g_pk[d]);
        float dx = ns.y - nd.y;
        float dy = ns.z - nd.z;
        float el = sqrtf(dx * dx + dy * dy + 1e-12f);
        float flux = ns.x - nd.x;
        float q = el * fabsf(flux);
        redAddV4(&g_acc[d], q, flux, 1.0f, 0.0f);
    } else {
        // ---- Ax = segment_sum(vals * pred[col_ind], row_idx); row_idx sorted
        long long i = (long long)(blockIdx.x - nbE) * blockDim.x + threadIdx.x;
        int lane = threadIdx.x & 31;
        int r = -1; float v = 0.f;
        if (i < e) {
            int c = g_is64[1] ? (int)((const long long*)cind)[i] : ((const int*)cind)[i];
            r     = g_is64[2] ? (int)((const long long*)ridx)[i] : ((const int*)ridx)[i];
            v = vals[i] * __ldg(&pred[c]);
        }
#pragma unroll
        for (int off = 1; off < 32; off <<= 1) {
            float ov = __shfl_up_sync(0xffffffffu, v, off);
            int   orr = __shfl_up_sync(0xffffffffu, r, off);
            if (lane >= off && orr == r) v += ov;
        }
        int rn = __shfl_down_sync(0xffffffffu, r, 1);
        if (r >= 0 && (lane == 31 || rn != r)) atomicAdd(&g_Ax[r], v);
    }
}

// w0_raw = 1 + qsum/deg, invdeg; grid-stride; one double atomic per block.
__global__ void k_node1(int n) {
    __shared__ double sm[8];
    double local = 0.0;
    int stride = gridDim.x * blockDim.x;
    for (int i = blockIdx.x * blockDim.x + threadIdx.x; i < n; i += stride) {
        float4 a = g_acc[i];
        float deg = fmaxf(a.z, 1.0f);
        float inv = 1.0f / deg;
        float w = 1.0f + a.x * inv;
        g_w0[i]  = w;
        g_inv[i] = inv;
        local += (double)w;
    }
    int lane = threadIdx.x & 31, wp = threadIdx.x >> 5;
    double s = warpSumD(local);
    if (lane == 0) sm[wp] = s;
    __syncthreads();
    if (wp == 0) {
        s = (lane < 8) ? sm[lane] : 0.0;
        s = warpSumD(s);
        if (lane == 0) atomicAdd(&g_red[0], s);
    }
}

// hop1: c1_raw[d] += w0_raw[src]
__global__ void k_hop1(long long e) {
    long long i = (long long)blockIdx.x * blockDim.x + threadIdx.x;
    if (i >= e) return;
    int2 sd = g_sd[i];
    atomicAdd(((float*)&g_acc[sd.y]) + 3, __ldg(&g_w0[sd.x]));
}

// c1n = c1_raw * invdeg (so hop2 gathers a single value)
__global__ void k_c1n(int n) {
    int i = blockIdx.x * blockDim.x + threadIdx.x;
    if (i < n) g_c1n[i] = ((const float*)&g_acc[i])[3] * g_inv[i];
}

// hop2: c2_raw[d] += c1n[src]
__global__ void k_hop2(long long e) {
    long long i = (long long)blockIdx.x * blockDim.x + threadIdx.x;
    if (i >= e) return;
    int2 sd = g_sd[i];
    atomicAdd(&g_c2[sd.y], __ldg(&g_c1n[sd.x]));
}

// Final node pass: grid-stride; all loss terms block-reduced in double.
// g_red: 1=pde_raw_sum, 2/3=inlet s/c, 4/5=outlet s/c, 6/7=wall s/c,
//        8/9=ic s/c, 10=cons_sum
__global__ void k_final(const float* __restrict__ pred,
                        const float* __restrict__ b,
                        const float* __restrict__ icv,
                        const unsigned char* __restrict__ icm,
                        const unsigned char* __restrict__ inm,
                        const unsigned char* __restrict__ outm,
                        const unsigned char* __restrict__ wm,
                        int n) {
    __shared__ double sm[10][8];
    double acc[10];
#pragma unroll
    for (int q = 0; q < 10; q++) acc[q] = 0.0;
    int stride = gridDim.x * blockDim.x;
    for (int i = blockIdx.x * blockDim.x + threadIdx.x; i < n; i += stride) {
        float4 a = g_acc[i];
        float inv = g_inv[i];
        float wc = g_w0[i] + 0.5f * (a.w * inv) + 0.25f * (g_c2[i] * inv);
        float res = g_Ax[i] - b[i];
        acc[0] += (double)(wc * res * res);           // pde, un-normalized
        float p = pred[i];
        if (inm[i])  { float t = p - 0.1f;   acc[1] += (double)(t * t); acc[2] += 1.0; }
        if (outm[i]) {                       acc[3] += (double)(p * p); acc[4] += 1.0; }
        if (wm[i])   {                       acc[5] += (double)(p * p); acc[6] += 1.0; }
        if (icm[i])  { float t = p - icv[i]; acc[7] += (double)(t * t); acc[8] += 1.0; }
        acc[9] += (double)a.y * (double)a.y;          // net^2
    }
    int lane = threadIdx.x & 31, wp = threadIdx.x >> 5;
#pragma unroll
    for (int q = 0; q < 10; q++) {
        double s = warpSumD(acc[q]);
        if (lane == 0) sm[q][wp] = s;
    }
    __syncthreads();
    if (wp == 0) {
#pragma unroll
        for (int q = 0; q < 10; q++) {
            double s = (lane < 8) ? sm[q][lane] : 0.0;
            s = warpSumD(s);
            if (lane == 0) atomicAdd(&g_red[1 + q], s);
        }
    }
}

__global__ void k_combine(float* out) {
    // pde = (sum wc_raw*r^2 / N) / mean(w0_raw) = red[1] / red[0]
    double pde  = g_red[1] / g_red[0];
    double bc   = g_red[2] / fmax(g_red[3], 1.0)
                + g_red[4] / fmax(g_red[5], 1.0)
                + g_red[6] / fmax(g_red[7], 1.0);
    double ic   = g_red[8] / fmax(g_red[9], 1.0);
    double N    = (double)NNODES;
    double cons = g_red[10] / N;
    out[0] = (float)(pde + bc + ic + cons);
}

// ---------------- launch ------------------------------------------------------
extern "C" void kernel_launch(void* const* d_in, const int* in_sizes, int n_in,
                              void* d_out, int out_size) {
    const float* pred  = (const float*)d_in[0];
    const float* feats = (const float*)d_in[1];
    const float* b     = (const float*)d_in[2];
    const float* vals  = (const float*)d_in[3];
    const float* icv   = (const float*)d_in[4];
    // d_in[5] = row_ptr (unused by the reference)
    const void* cind   = d_in[6];
    const void* ridx   = d_in[7];
    const void* eidx   = d_in[8];
    const unsigned char* icm  = (const unsigned char*)d_in[9];
    const unsigned char* inm  = (const unsigned char*)d_in[10];
    const unsigned char* outm = (const unsigned char*)d_in[11];
    const unsigned char* wm   = (const unsigned char*)d_in[12];

    int       n = in_sizes[0];
    long long e = (long long)in_sizes[3];

    int      nb_n = (n + 255) / 256;
    unsigned nb_e = (unsigned)((e + 255) / 256);

    k_init   <<<nb_n, 256>>>(eidx, 2 * e, cind, e, ridx, pred, feats, n);
    k_edge_ax<<<2 * nb_e, 256>>>(eidx, pred, cind, ridx, vals, e, nb_e);
    k_node1  <<<148, 256>>>(n);
    k_hop1   <<<nb_e, 256>>>(e);
    k_c1n    <<<nb_n, 256>>>(n);
    k_hop2   <<<nb_e, 256>>>(e);
    k_final  <<<148, 256>>>(pred, b, icv, icm, inm, outm, wm, n);
    k_combine<<<1, 1>>>((float*)d_out);
}